// round 10
// baseline (speedup 1.0000x reference)
#include <cuda_runtime.h>
#include <cstdint>

#define BATCH  262144
#define NTILES 2048

// ---------------- scratch (__device__ globals) --------------------------------
__device__ unsigned char g_xa[BATCH * 128];     // x in e4m3, K padded 64->128
__device__ unsigned char g_h0[BATCH * 256];     // activations ping (e4m3)
__device__ unsigned char g_h1[BATCH * 256];     // activations pong (e4m3)
__device__ unsigned char g_wt[256 * 256];       // prepped W^T e4m3: [n][k]
__device__ float g_bias[256];                   // summed bias (fp32)
__device__ float g_sumsq[32];                   // slots 0..3 per-node; [16] output

// ---------------- helpers -----------------------------------------------------
__device__ __forceinline__ uint32_t smem_u32(const void* p) {
    uint32_t a;
    asm("{ .reg .u64 t; cvta.to.shared.u64 t, %1; cvt.u32.u64 %0, t; }" : "=r"(a) : "l"(p));
    return a;
}
__device__ __forceinline__ uint32_t sw128(uint32_t off) {
    return off ^ ((off >> 3) & 0x70);
}
__device__ __forceinline__ void cp16(uint32_t s, const void* g) {
    asm volatile("cp.async.cg.shared.global [%0], [%1], 16;" :: "r"(s), "l"(g));
}
__device__ __forceinline__ void ldm_x4(uint32_t* r, uint32_t addr) {
    asm volatile("ldmatrix.sync.aligned.m8n8.x4.shared.b16 {%0,%1,%2,%3}, [%4];"
                 : "=r"(r[0]), "=r"(r[1]), "=r"(r[2]), "=r"(r[3]) : "r"(addr));
}
__device__ __forceinline__ void mma_fp8(float* d, const uint32_t* a, const uint32_t* b) {
    asm volatile(
        "mma.sync.aligned.m16n8k32.row.col.f32.e4m3.e4m3.f32 "
        "{%0,%1,%2,%3}, {%4,%5,%6,%7}, {%8,%9}, {%0,%1,%2,%3};"
        : "+f"(d[0]), "+f"(d[1]), "+f"(d[2]), "+f"(d[3])
        : "r"(a[0]), "r"(a[1]), "r"(a[2]), "r"(a[3]), "r"(b[0]), "r"(b[1]));
}
__device__ __forceinline__ uint32_t f2e4m3x2(float lo, float hi) {
    uint16_t r;
    asm("cvt.rn.satfinite.e4m3x2.f32 %0, %1, %2;" : "=h"(r) : "f"(hi), "f"(lo));
    return (uint32_t)r;
}

// ---------------- tiny prep kernels -------------------------------------------
__global__ void zero_kernel() { if (threadIdx.x < 32) g_sumsq[threadIdx.x] = 0.f; }

// x [B,64] fp32 -> g_xa [B,128] e4m3 (upper 64 zero)
__global__ void convert_x(const float* __restrict__ x) {
    int t = blockIdx.x * 256 + threadIdx.x;               // 1,048,576
    int r = t >> 2, q = t & 3;
    const float4* xr = (const float4*)(x + (size_t)r * 64 + q * 16);
    uint32_t w[4];
    #pragma unroll
    for (int i = 0; i < 4; i++) {
        float4 v = xr[i];
        w[i] = f2e4m3x2(v.x, v.y) | (f2e4m3x2(v.z, v.w) << 16);
    }
    *(uint4*)(g_xa + (size_t)r * 128 + q * 16)      = make_uint4(w[0], w[1], w[2], w[3]);
    *(uint4*)(g_xa + (size_t)r * 128 + 64 + q * 16) = make_uint4(0, 0, 0, 0);
}

// rows of 128B (K=128 padded): [j][w<64]=W_in[kO][v][w], rest 0
__global__ void prep_in(const float* __restrict__ W, const float* __restrict__ b) {
    int e = blockIdx.x * 256 + threadIdx.x;               // 16384 uint16 slots
    int j = e >> 6, c = e & 63;
    uint16_t out = 0;
    if (c < 32) {
        int w = c * 2;
        const float* src = W + ((j >> 6) << 12) + ((j & 63) << 6) + w;
        out = (uint16_t)f2e4m3x2(src[0], src[1]);
    }
    ((uint16_t*)g_wt)[e] = out;
    if (e < 256) g_bias[e] = b[e];
}

// g_wt[j][p*64+w] = W_mid[l][p][kO][v][w] * rsqrt(ss[p]) * 4096 ; j=kO*64+v
__global__ void prep_mid(const float* __restrict__ W, const float* __restrict__ b,
                         int l, int slot_in) {
    int e = blockIdx.x * 256 + threadIdx.x;               // 32768 uint16 slots
    int j = e >> 7, c = e & 127;
    int kO = j >> 6, v = j & 63, p = c >> 5, w = (c & 31) * 2;
    float s = rsqrtf(g_sumsq[(slot_in << 2) + p]) * 4096.f;
    const float* src = W + (((l * 4 + p) * 4 + kO) << 12) + (v << 6) + w;
    ((uint16_t*)g_wt)[e] = (uint16_t)f2e4m3x2(src[0] * s, src[1] * s);
    if (e < 256) {
        int kk = e >> 6, vv = e & 63;
        float bs = 0.f;
        #pragma unroll
        for (int p2 = 0; p2 < 4; p2++) bs += b[(((l * 4 + p2) * 4 + kk) << 6) + vv];
        g_bias[e] = bs;
    }
}

// g_wt[v][p*64+w] = W_out[p][v][w] * rsqrt(ss[p]) * 4096
__global__ void prep_out(const float* __restrict__ W, const float* __restrict__ b,
                         int slot_in) {
    int e = blockIdx.x * 256 + threadIdx.x;               // 8192 uint16 slots
    int v = e >> 7, c = e & 127;
    int p = c >> 5, w = (c & 31) * 2;
    float s = rsqrtf(g_sumsq[(slot_in << 2) + p]) * 4096.f;
    const float* src = W + (p << 12) + (v << 6) + w;
    ((uint16_t*)g_wt)[e] = (uint16_t)f2e4m3x2(src[0] * s, src[1] * s);
    if (e < 64) {
        float bs = 0.f;
        #pragma unroll
        for (int p2 = 0; p2 < 4; p2++) bs += b[(p2 << 6) + e];
        g_bias[e] = bs;
    }
}

// ---------------- persistent fp8 QMMA GEMM ------------------------------------
// Each CTA walks row-tiles bid, bid+G, ... Weights resident in smem all layer;
// A chunks (128 rows x 128B e4m3) stream through a 4-deep cp.async ring
// continuously ACROSS tiles. Epilogue staged in smem -> STG.128 coalesced.
template <int K, int BN, bool OUTF32>
__global__ void __launch_bounds__(512, 1) mma_gemm(
        int asel, int ysel, float* __restrict__ Yf, float invS, int slot_out)
{
    constexpr int NCH   = K / 128;               // chunks per tile (1 or 2)
    constexpr int LOGC  = (NCH == 2) ? 1 : 0;
    constexpr int ABY   = 128 * 128;             // A chunk: 16 KB
    constexpr int BSLAB = BN * 128;              // weight slab per chunk
    constexpr int WTOT  = BSLAB * NCH;
    constexpr int S     = 4;                     // ring depth
    constexpr int NWN   = (BN == 256) ? 4 : 2;
    constexpr int WN    = BN / NWN;              // 64 or 32
    constexpr int NWM   = 16 / NWN;
    constexpr int WM    = 128 / NWM;             // 32 or 16
    constexpr int MI    = WM / 16;               // 2 or 1
    constexpr int NJ    = WN / 8;                // 8 or 4
    constexpr int STRIDE = 288;                  // staged row: 256B data + pad
    constexpr int STAGEOFF = WTOT + S * ABY;

    extern __shared__ char smem[];
    __shared__ float s_bias[256];

    const char* Ab = (const char*)((asel == 0) ? g_xa : (asel == 1) ? g_h0 : g_h1);
    unsigned char* Yb = (ysel == 1) ? g_h0 : g_h1;

    const int tid = threadIdx.x, wid = tid >> 5, lane = tid & 31;
    const int bid = blockIdx.x, G = gridDim.x;
    const int wm = (wid / NWN) * WM;
    const int wn = (wid % NWN) * WN;
    const int lg = lane >> 3, rin = lane & 7;

    if (tid < 256) s_bias[tid] = (tid < BN) ? g_bias[tid] : 0.f;

    const uint32_t smb = smem_u32(smem);
    char* stage = smem + STAGEOFF;
    const int ntile = (NTILES - 1 - bid) / G + 1;
    const int total = ntile << LOGC;

    // ---- weights: load once, resident (cp.async group 0) ----
    #pragma unroll
    for (int c = 0; c < NCH; c++)
        for (int e = tid; e < BN * 8; e += 512) {
            int n = e >> 3, q = e & 7;
            cp16(smb + c * BSLAB + sw128((n << 7) + (q << 4)),
                 (const char*)g_wt + (size_t)n * K + c * 128 + q * 16);
        }
    asm volatile("cp.async.commit_group;" ::: "memory");

    auto issueA = [&](int gch) {
        uint32_t sA = smb + WTOT + (gch & 3) * ABY;
        int c = gch & (NCH - 1);
        size_t rowbase = (size_t)((bid + (gch >> LOGC) * G) << 7);
        #pragma unroll
        for (int i = 0; i < 2; i++) {
            int e = tid + i * 512, r = e >> 3, q = e & 7;
            cp16(sA + sw128((r << 7) + (q << 4)),
                 Ab + (rowbase + r) * K + c * 128 + q * 16);
        }
        asm volatile("cp.async.commit_group;" ::: "memory");
    };

    for (int g0 = 0; g0 < S - 1; g0++) issueA(g0);   // total >= 13 always

    float acc[MI][NJ][4];
    #pragma unroll
    for (int m = 0; m < MI; m++)
        #pragma unroll
        for (int n = 0; n < NJ; n++)
            #pragma unroll
            for (int r = 0; r < 4; r++) acc[m][n][r] = 0.f;
    float lsq = 0.f;
    const int crow = lane >> 2, ccol = (lane & 3) << 1;

    for (int gch = 0; gch < total; gch++) {
        int rem = total - gch;
        if (rem > 2)       asm volatile("cp.async.wait_group 2;" ::: "memory");
        else if (rem == 2) asm volatile("cp.async.wait_group 1;" ::: "memory");
        else               asm volatile("cp.async.wait_group 0;" ::: "memory");
        __syncthreads();
        if (gch + S - 1 < total) issueA(gch + S - 1);

        const int c = gch & (NCH - 1);
        const uint32_t sA = smb + WTOT + (gch & 3) * ABY;
        const uint32_t sB = smb + c * BSLAB;

        #pragma unroll
        for (int kk = 0; kk < 4; kk++) {                  // 4 x k32 = 128B of K
            uint32_t af[MI][4];
            #pragma unroll
            for (int mi = 0; mi < MI; mi++) {
                int row = wm + mi * 16 + ((lg & 1) << 3) + rin;
                ldm_x4(af[mi], sA + sw128((row << 7) + kk * 32 + ((lg >> 1) << 4)));
            }
            uint32_t bf[NJ][2];
            #pragma unroll
            for (int njp = 0; njp < NJ / 2; njp++) {
                int row = wn + njp * 16 + ((lg >> 1) << 3) + rin;
                uint32_t t[4];
                ldm_x4(t, sB + sw128((row << 7) + kk * 32 + ((lg & 1) << 4)));
                bf[njp * 2][0]     = t[0]; bf[njp * 2][1]     = t[1];
                bf[njp * 2 + 1][0] = t[2]; bf[njp * 2 + 1][1] = t[3];
            }
            #pragma unroll
            for (int mi = 0; mi < MI; mi++)
                #pragma unroll
                for (int nj = 0; nj < NJ; nj++)
                    mma_fp8(acc[mi][nj], af[mi], bf[nj]);
        }

        if (c == NCH - 1) {
            // ---- tile epilogue: scale, bias, sumsq; stage; coalesced store ---
            int row0 = (bid + (gch >> LOGC) * G) << 7;
            #pragma unroll
            for (int mi = 0; mi < MI; mi++) {
                #pragma unroll
                for (int nj = 0; nj < NJ; nj++) {
                    int col = wn + nj * 8 + ccol;
                    float b0 = s_bias[col], b1 = s_bias[col + 1];
                    #pragma unroll
                    for (int h = 0; h < 2; h++) {
                        int r = wm + mi * 16 + crow + h * 8;
                        float v0 = fmaf(acc[mi][nj][2 * h],     invS, b0);
                        float v1 = fmaf(acc[mi][nj][2 * h + 1], invS, b1);
                        lsq += v0 * v0 + v1 * v1;
                        if (OUTF32)
                            *(float2*)(stage + r * STRIDE + col * 4) =
                                make_float2(v0, v1);
                        else
                            *(uint16_t*)(stage + r * STRIDE + col) =
                                (uint16_t)f2e4m3x2(v0, v1);
                        acc[mi][nj][2 * h] = 0.f;
                        acc[mi][nj][2 * h + 1] = 0.f;
                    }
                }
            }
            __syncthreads();
            // 128 rows x 256B contiguous (fp8 full row / fp32 64 cols)
            char* gout = OUTF32 ? (char*)Yf : (char*)Yb;
            #pragma unroll
            for (int e = tid; e < 2048; e += 512) {
                int r = e >> 4, cB = (e & 15) << 4;
                *(uint4*)(gout + (size_t)(row0 + r) * 256 + cB) =
                    *(const uint4*)(stage + r * STRIDE + cB);
            }
        }
    }

    // ---- per-node sumsq: one atomic per warp per layer ----
    #pragma unroll
    for (int off = 16; off; off >>= 1)
        lsq += __shfl_xor_sync(0xffffffff, lsq, off);
    if (lane == 0)
        atomicAdd(&g_sumsq[(slot_out << 2) + (wn >> 6)], lsq);
}

// ---------------- finalize ----------------------------------------------------
__global__ void finalize_kernel(float* __restrict__ out) {
    float s = rsqrtf(g_sumsq[16]);
    int i = blockIdx.x * 256 + threadIdx.x;               // 4,194,304 float4
    float4* o = (float4*)out;
    float4 v = o[i];
    v.x *= s; v.y *= s; v.z *= s; v.w *= s;
    o[i] = v;
}

// ---------------- launch ------------------------------------------------------
extern "C" void kernel_launch(void* const* d_in, const int* in_sizes, int n_in,
                              void* d_out, int out_size)
{
    const float* x     = (const float*)d_in[0];
    const float* W_in  = (const float*)d_in[1];
    const float* b_in  = (const float*)d_in[2];
    const float* W_mid = (const float*)d_in[3];
    const float* b_mid = (const float*)d_in[4];
    const float* W_out = (const float*)d_in[5];
    const float* b_out = (const float*)d_in[6];
    float* out = (float*)d_out;

    int sms = 148;
    cudaDeviceGetAttribute(&sms, cudaDevAttrMultiProcessorCount, 0);

    const int STG = 128 * 288;                             // 36 KB epilogue stage
    const int SM_L1  = 256 * 128 * 1 + 4 * 128 * 128 + STG;   // 132 KB
    const int SM_MID = 256 * 128 * 2 + 4 * 128 * 128 + STG;   // 164 KB
    const int SM_OUT = 64 * 128 * 2  + 4 * 128 * 128 + STG;   // 116 KB
    cudaFuncSetAttribute(mma_gemm<128, 256, false>,
                         cudaFuncAttributeMaxDynamicSharedMemorySize, SM_L1);
    cudaFuncSetAttribute(mma_gemm<256, 256, false>,
                         cudaFuncAttributeMaxDynamicSharedMemorySize, SM_MID);
    cudaFuncSetAttribute(mma_gemm<256, 64, true>,
                         cudaFuncAttributeMaxDynamicSharedMemorySize, SM_OUT);

    zero_kernel<<<1, 32>>>();
    convert_x<<<4096, 256>>>(x);

    // layer 1: g_xa [B,128pad] -> g_h0 (e4m3), sumsq slot 0; invS = 1
    prep_in<<<64, 256>>>(W_in, b_in);
    mma_gemm<128, 256, false><<<sms, 512, SM_L1>>>(0, 1, nullptr, 1.0f, 0);

    // 3 mid transitions (rsqrt*4096 folded into weights; epilogue invS=1/4096)
    int a = 1;                                             // 1 = g_h0, 2 = g_h1
    for (int l = 0; l < 3; l++) {
        prep_mid<<<128, 256>>>(W_mid, b_mid, l, l);
        mma_gemm<256, 256, false><<<sms, 512, SM_MID>>>(a, 3 - a, nullptr,
                                                        1.0f / 4096.f, l + 1);
        a = 3 - a;
    }

    // out layer -> d_out raw fp32 (sumsq slot 4 -> g_sumsq[16]), then normalize
    prep_out<<<32, 256>>>(W_out, b_out, 3);
    mma_gemm<256, 64, true><<<sms, 512, SM_OUT>>>(a, 0, out, 1.0f / 4096.f, 4);
    finalize_kernel<<<16384, 256>>>(out);
}

// round 11
// speedup vs baseline: 1.0505x; 1.0505x over previous
#include <cuda_runtime.h>
#include <cuda_bf16.h>
#include <cstdint>

#define BATCH  262144
#define NTILES 2048

// ---------------- scratch (__device__ globals) --------------------------------
__device__ __nv_bfloat16 g_hb0[BATCH * 256];    // activations ping
__device__ __nv_bfloat16 g_hb1[BATCH * 256];    // activations pong
__device__ __nv_bfloat16 g_wt[256 * 256];       // prepped W^T bf16: [n][k]
__device__ float g_bias[256];                   // summed bias (fp32)
__device__ float g_sumsq[32];                   // slots 0..3 per-node; [16] output
__device__ int   g_barrier;                     // grid barrier for out kernel

// ---------------- helpers -----------------------------------------------------
__device__ __forceinline__ uint32_t smem_u32(const void* p) {
    uint32_t a;
    asm("{ .reg .u64 t; cvta.to.shared.u64 t, %1; cvt.u32.u64 %0, t; }" : "=r"(a) : "l"(p));
    return a;
}
__device__ __forceinline__ uint32_t sw128(uint32_t off) {
    return off ^ ((off >> 3) & 0x70);
}
__device__ __forceinline__ void cp16(uint32_t s, const void* g) {
    asm volatile("cp.async.cg.shared.global [%0], [%1], 16;" :: "r"(s), "l"(g));
}
__device__ __forceinline__ void ldm_x4(uint32_t* r, uint32_t addr) {
    asm volatile("ldmatrix.sync.aligned.m8n8.x4.shared.b16 {%0,%1,%2,%3}, [%4];"
                 : "=r"(r[0]), "=r"(r[1]), "=r"(r[2]), "=r"(r[3]) : "r"(addr));
}
__device__ __forceinline__ void mma16816(float* d, const uint32_t* a, const uint32_t* b) {
    asm volatile(
        "mma.sync.aligned.m16n8k16.row.col.f32.bf16.bf16.f32 "
        "{%0,%1,%2,%3}, {%4,%5,%6,%7}, {%8,%9}, {%0,%1,%2,%3};"
        : "+f"(d[0]), "+f"(d[1]), "+f"(d[2]), "+f"(d[3])
        : "r"(a[0]), "r"(a[1]), "r"(a[2]), "r"(a[3]), "r"(b[0]), "r"(b[1]));
}

// ---------------- tiny prep kernels -------------------------------------------
__global__ void zero_kernel() {
    if (threadIdx.x < 32) g_sumsq[threadIdx.x] = 0.f;
    if (threadIdx.x == 0) g_barrier = 0;
}

// g_wt[j*64 + w] = W_in[kO][v][w], j = kO*64+v
__global__ void prep_in(const float* __restrict__ W, const float* __restrict__ b) {
    int e = blockIdx.x * 256 + threadIdx.x;                // 16384
    int j = e >> 6, w = e & 63;
    g_wt[e] = __float2bfloat16(W[((j >> 6) << 12) + ((j & 63) << 6) + w]);
    if (e < 256) g_bias[e] = b[e];
}

// g_wt[j*256 + p*64+w] = W_mid[l][p][kO][v][w] * rsqrt(ss[p]) ; j=kO*64+v
__global__ void prep_mid(const float* __restrict__ W, const float* __restrict__ b,
                         int l, int slot_in) {
    int e = blockIdx.x * 256 + threadIdx.x;                // 65536
    int j = e >> 8, i = e & 255;
    int kO = j >> 6, v = j & 63, p = i >> 6, w = i & 63;
    float s = rsqrtf(g_sumsq[(slot_in << 2) + p]);
    g_wt[e] = __float2bfloat16(W[(((l * 4 + p) * 4 + kO) << 12) + (v << 6) + w] * s);
    if (e < 256) {
        int kk = e >> 6, vv = e & 63;
        float bs = 0.f;
        #pragma unroll
        for (int p2 = 0; p2 < 4; p2++) bs += b[(((l * 4 + p2) * 4 + kk) << 6) + vv];
        g_bias[e] = bs;
    }
}

// g_wt[v*256 + p*64+w] = W_out[p][v][w] * rsqrt(ss[p])
__global__ void prep_out(const float* __restrict__ W, const float* __restrict__ b,
                         int slot_in) {
    int e = blockIdx.x * 256 + threadIdx.x;                // 16384
    int v = e >> 8, i = e & 255, p = i >> 6, w = i & 63;
    float s = rsqrtf(g_sumsq[(slot_in << 2) + p]);
    g_wt[e] = __float2bfloat16(W[(p << 12) + (v << 6) + w] * s);
    if (e < 64) {
        float bs = 0.f;
        #pragma unroll
        for (int p2 = 0; p2 < 4; p2++) bs += b[(p2 << 6) + e];
        g_bias[e] = bs;
    }
}

// ---------------- persistent bf16 HMMA GEMM -----------------------------------
// AF32: A is fp32 x[B,64], converted in-smem to bf16 (kills convert_x pass).
// NCH==4: paired-chunk mainloop (1 barrier / 128 K) with 3-pair (6 chunk) ring.
// OUTF32: fp32 output + fused whole-tensor normalize via device grid barrier.
template <int K, int BN, bool OUTF32, bool AF32>
__global__ void __launch_bounds__(512, 1) mma_gemm(
        const float* __restrict__ Xf, int asel, int ysel,
        float* __restrict__ Yf, int slot_out)
{
    constexpr int NCH   = K / 64;                // chunks (64-K each) per tile
    constexpr int ABY   = 128 * 128;             // bf16 chunk tile: 16 KB
    constexpr int FBY   = 128 * 256;             // fp32 stage (AF32): 32 KB
    constexpr int SLOT  = AF32 ? (ABY + FBY) : ABY;
    constexpr int BSLAB = BN * 128;              // weight slab per chunk
    constexpr int WTOT  = BSLAB * NCH;
    constexpr int NWN   = (BN == 256) ? 4 : 2;
    constexpr int WN    = BN / NWN;              // 64 or 32
    constexpr int NWM   = 16 / NWN;
    constexpr int WM    = 128 / NWM;             // 32 or 16
    constexpr int MI    = WM / 16;               // 2 or 1
    constexpr int NJ    = WN / 8;                // 8 or 4

    extern __shared__ char smem[];
    __shared__ float s_bias[256];

    const char* Ab = (const char*)((asel == 1) ? g_hb0 : g_hb1);
    __nv_bfloat16* Yb = (ysel == 1) ? g_hb0 : g_hb1;

    const int tid = threadIdx.x, wid = tid >> 5, lane = tid & 31;
    const int bid = blockIdx.x, G = gridDim.x;
    const int wm = (wid / NWN) * WM;
    const int wn = (wid % NWN) * WN;
    const int lg = lane >> 3, rin = lane & 7;

    if (tid < 256) s_bias[tid] = g_bias[tid];

    const uint32_t smb = smem_u32(smem);
    const int ntile = (NTILES - 1 - bid) / G + 1;

    // ---- weights: load once, resident (first cp.async group) ----
    #pragma unroll
    for (int c = 0; c < NCH; c++)
        for (int e = tid; e < BN * 8; e += 512) {
            int n = e >> 3, q = e & 7;
            cp16(smb + c * BSLAB + sw128((n << 7) + (q << 4)),
                 (const char*)g_wt + (size_t)n * (2 * K) + c * 128 + q * 16);
        }
    asm volatile("cp.async.commit_group;" ::: "memory");

    float acc[MI][NJ][4];
    #pragma unroll
    for (int m = 0; m < MI; m++)
        #pragma unroll
        for (int n = 0; n < NJ; n++)
            #pragma unroll
            for (int r = 0; r < 4; r++) acc[m][n][r] = 0.f;
    float lsq = 0.f;
    const int crow = lane >> 2, ccol = (lane & 3) << 1;

    // ---- shared fragment compute for one 64-K chunk ----
    auto compute_chunk = [&](uint32_t sA, uint32_t sB) {
        #pragma unroll
        for (int k16 = 0; k16 < 4; k16++) {
            uint32_t af[MI][4];
            #pragma unroll
            for (int mi = 0; mi < MI; mi++) {
                int row = wm + mi * 16 + ((lg & 1) << 3) + rin;
                ldm_x4(af[mi], sA + sw128((row << 7) + k16 * 32 + ((lg >> 1) << 4)));
            }
            uint32_t bf[NJ][2];
            #pragma unroll
            for (int njp = 0; njp < NJ / 2; njp++) {
                int row = wn + njp * 16 + ((lg >> 1) << 3) + rin;
                uint32_t t[4];
                ldm_x4(t, sB + sw128((row << 7) + k16 * 32 + ((lg & 1) << 4)));
                bf[njp * 2][0]     = t[0]; bf[njp * 2][1]     = t[1];
                bf[njp * 2 + 1][0] = t[2]; bf[njp * 2 + 1][1] = t[3];
            }
            #pragma unroll
            for (int mi = 0; mi < MI; mi++)
                #pragma unroll
                for (int nj = 0; nj < NJ; nj++)
                    mma16816(acc[mi][nj], af[mi], bf[nj]);
        }
    };

    auto epilogue = [&](int row0) {
        #pragma unroll
        for (int mi = 0; mi < MI; mi++) {
            #pragma unroll
            for (int nj = 0; nj < NJ; nj++) {
                int col = wn + nj * 8 + ccol;
                float b0 = s_bias[col], b1 = s_bias[col + 1];
                #pragma unroll
                for (int h = 0; h < 2; h++) {
                    int row = row0 + wm + mi * 16 + crow + h * 8;
                    float v0 = acc[mi][nj][2 * h]     + b0;
                    float v1 = acc[mi][nj][2 * h + 1] + b1;
                    lsq += v0 * v0 + v1 * v1;
                    if (OUTF32)
                        *(float2*)(Yf + (size_t)row * 64 + col) = make_float2(v0, v1);
                    else
                        *(__nv_bfloat162*)(Yb + (size_t)row * 256 + col) =
                            __floats2bfloat162_rn(v0, v1);
                    acc[mi][nj][2 * h] = 0.f;
                    acc[mi][nj][2 * h + 1] = 0.f;
                }
            }
        }
    };

    if constexpr (NCH == 1) {
        // ======== layer-1 path: chunk ring S=4, fp32 in-smem convert ========
        const int total = ntile;
        auto issueA = [&](int g) {
            uint32_t sF = smb + WTOT + (g & 3) * SLOT + ABY;
            size_t rowbase = (size_t)((bid + g * G) << 7);
            #pragma unroll
            for (int i = 0; i < 4; i++) {                  // 2048 x 16B fp32
                int e = tid + i * 512, r = e >> 4, q = e & 15;
                cp16(sF + (r << 8) + (q << 4),
                     (const char*)Xf + (rowbase + r) * 256 + q * 16);
            }
            asm volatile("cp.async.commit_group;" ::: "memory");
        };
        issueA(0); issueA(1); issueA(2);

        for (int g = 0; g < total; g++) {
            int rem = total - g;
            if (rem > 2)       asm volatile("cp.async.wait_group 2;" ::: "memory");
            else if (rem == 2) asm volatile("cp.async.wait_group 1;" ::: "memory");
            else               asm volatile("cp.async.wait_group 0;" ::: "memory");
            __syncthreads();
            if (g + 3 < total) issueA(g + 3);

            // in-smem convert: fp32 stage -> SW128 bf16 tile
            uint32_t slotb = smb + WTOT + (g & 3) * SLOT;
            {
                int row = tid >> 2, seg = tid & 3;
                const float4* fs = (const float4*)(smem + WTOT + (g & 3) * SLOT +
                                                   ABY + row * 256 + seg * 64);
                uint32_t pk[8];
                #pragma unroll
                for (int i = 0; i < 4; i++) {
                    float4 v = fs[i];
                    __nv_bfloat162 h0 = __floats2bfloat162_rn(v.x, v.y);
                    __nv_bfloat162 h1 = __floats2bfloat162_rn(v.z, v.w);
                    pk[2 * i]     = *(uint32_t*)&h0;
                    pk[2 * i + 1] = *(uint32_t*)&h1;
                }
                char* base = smem + WTOT + (g & 3) * SLOT;
                *(uint4*)(base + sw128((row << 7) + seg * 32)) =
                    make_uint4(pk[0], pk[1], pk[2], pk[3]);
                *(uint4*)(base + sw128((row << 7) + seg * 32 + 16)) =
                    make_uint4(pk[4], pk[5], pk[6], pk[7]);
            }
            __syncthreads();

            compute_chunk(slotb, smb);                     // sB = weights slab 0
            epilogue((bid + g * G) << 7);
        }
    } else {
        // ======== mid/out path: paired chunks, 3-pair (6 chunk) ring ========
        const int npair = ntile * 2;                       // 2 pairs per tile
        auto issuePair = [&](int p) {
            #pragma unroll
            for (int half = 0; half < 2; half++) {
                int ch = 2 * p + half;
                uint32_t sA = smb + WTOT + ((p % 3) * 2 + half) * ABY;
                int c = ch & 3;
                size_t rowbase = (size_t)((bid + (ch >> 2) * G) << 7);
                #pragma unroll
                for (int i = 0; i < 2; i++) {
                    int e = tid + i * 512, r = e >> 3, q = e & 7;
                    cp16(sA + sw128((r << 7) + (q << 4)),
                         Ab + (rowbase + r) * (2 * K) + c * 128 + q * 16);
                }
            }
            asm volatile("cp.async.commit_group;" ::: "memory");
        };
        issuePair(0); issuePair(1);                        // npair >= 26 always

        for (int p = 0; p < npair; p++) {
            if (p + 1 < npair) asm volatile("cp.async.wait_group 1;" ::: "memory");
            else               asm volatile("cp.async.wait_group 0;" ::: "memory");
            __syncthreads();
            if (p + 2 < npair) issuePair(p + 2);

            #pragma unroll
            for (int half = 0; half < 2; half++) {
                int ch = 2 * p + half;
                int c = ch & 3;
                compute_chunk(smb + WTOT + ((p % 3) * 2 + half) * ABY,
                              smb + c * BSLAB);
                if (c == 3) epilogue((bid + (ch >> 2) * G) << 7);
            }
        }
    }

    // ---- per-node sumsq: one atomic per warp per layer ----
    #pragma unroll
    for (int off = 16; off; off >>= 1)
        lsq += __shfl_xor_sync(0xffffffff, lsq, off);
    if (lane == 0)
        atomicAdd(&g_sumsq[(slot_out << 2) + (wn >> 6)], lsq);

    if constexpr (OUTF32) {
        // ---- fused finalize: grid barrier, then rescale own tiles ----
        if (tid == 0) {
            __threadfence();
            atomicAdd(&g_barrier, 1);
            while (*((volatile int*)&g_barrier) < G) { }
        }
        __syncthreads();
        float s = rsqrtf(*((volatile float*)&g_sumsq[16]));
        for (int t = 0; t < ntile; t++) {
            int row0 = (bid + t * G) << 7;
            #pragma unroll
            for (int e = tid; e < 2048; e += 512) {        // 128 rows x 16 float4
                int r = e >> 4, c4 = e & 15;
                float4* p4 = (float4*)(Yf + (size_t)(row0 + r) * 64) + c4;
                float4 v = *p4;
                v.x *= s; v.y *= s; v.z *= s; v.w *= s;
                *p4 = v;
            }
        }
    }
}

// ---------------- launch ------------------------------------------------------
extern "C" void kernel_launch(void* const* d_in, const int* in_sizes, int n_in,
                              void* d_out, int out_size)
{
    const float* x     = (const float*)d_in[0];
    const float* W_in  = (const float*)d_in[1];
    const float* b_in  = (const float*)d_in[2];
    const float* W_mid = (const float*)d_in[3];
    const float* b_mid = (const float*)d_in[4];
    const float* W_out = (const float*)d_in[5];
    const float* b_out = (const float*)d_in[6];
    float* out = (float*)d_out;

    int sms = 148;
    cudaDeviceGetAttribute(&sms, cudaDevAttrMultiProcessorCount, 0);

    const int SM_L1  = 256 * 128 * 1 + 4 * (128 * 128 + 128 * 256); // 224 KB
    const int SM_MID = 256 * 128 * 4 + 6 * 128 * 128;               // 224 KB
    const int SM_OUT = 64 * 128 * 4  + 6 * 128 * 128;               // 128 KB
    cudaFuncSetAttribute(mma_gemm<64, 256, false, true>,
                         cudaFuncAttributeMaxDynamicSharedMemorySize, SM_L1);
    cudaFuncSetAttribute(mma_gemm<256, 256, false, false>,
                         cudaFuncAttributeMaxDynamicSharedMemorySize, SM_MID);
    cudaFuncSetAttribute(mma_gemm<256, 64, true, false>,
                         cudaFuncAttributeMaxDynamicSharedMemorySize, SM_OUT);

    zero_kernel<<<1, 32>>>();

    // layer 1: x fp32 [B,64] -> g_hb0 (bf16), sumsq slot 0 (fused convert)
    prep_in<<<64, 256>>>(W_in, b_in);
    mma_gemm<64, 256, false, true><<<sms, 512, SM_L1>>>(x, 0, 1, nullptr, 0);

    // 3 mid transitions (norm scalars folded into weights by prep)
    int a = 1;                                             // 1 = g_hb0, 2 = g_hb1
    for (int l = 0; l < 3; l++) {
        prep_mid<<<256, 256>>>(W_mid, b_mid, l, l);
        mma_gemm<256, 256, false, false><<<sms, 512, SM_MID>>>(nullptr, a, 3 - a,
                                                               nullptr, l + 1);
        a = 3 - a;
    }

    // out layer -> d_out fp32 with fused whole-tensor normalize (slot 4)
    prep_out<<<64, 256>>>(W_out, b_out, 3);
    mma_gemm<256, 64, true, false><<<sms, 512, SM_OUT>>>(nullptr, a, 0, out, 4);
}